// round 15
// baseline (speedup 1.0000x reference)
#include <cuda_runtime.h>
#include <cuda_fp16.h>
#include <math.h>
#include <stdint.h>

#define D_MODEL 1024
#define N_HEAD  16
#define BB      2
#define TT      2048
#define ROWS    (BB*TT)      // 4096
#define EXPAND  4

// ---------------- scratch (device globals; no allocation allowed) ----------
__device__ __half g_a  [ROWS * D_MODEL];            // activations (ln1/y/ln2)
__device__ __half g_h  [ROWS * EXPAND * D_MODEL];   // qkv (3C) / mlp hidden (4C)
__device__ __half g_w0 [3 * D_MODEL * D_MODEL];     // attn_w^T
__device__ __half g_w1 [D_MODEL * D_MODEL];         // proj_w^T
__device__ __half g_w2 [EXPAND * D_MODEL * D_MODEL];// fc_w^T
__device__ __half g_w3 [EXPAND * D_MODEL * D_MODEL];// fc2_w^T
__device__ float  g_x1 [ROWS * D_MODEL];

// ================= helpers ==================================================
__device__ __forceinline__ uint32_t smem_to_u32(const void* p) {
    uint32_t a;
    asm("{ .reg .u64 t; cvta.to.shared.u64 t, %1; cvt.u32.u64 %0, t; }" : "=r"(a) : "l"(p));
    return a;
}
#define SMEM_SWIZZLE_128B(off) ((off) ^ (((off) >> 3) & 0x70))

#define CP_ASYNC16(dst_u32, src_ptr) \
    asm volatile("cp.async.cg.shared.global [%0], [%1], 16;" :: "r"(dst_u32), "l"(src_ptr))
#define CP_COMMIT() asm volatile("cp.async.commit_group;" ::: "memory")
#define CP_WAIT0()  asm volatile("cp.async.wait_group 0;" ::: "memory")
#define CP_WAIT1()  asm volatile("cp.async.wait_group 1;" ::: "memory")

#define LDMATRIX_X4(r0, r1, r2, r3, addr) \
    asm volatile("ldmatrix.sync.aligned.m8n8.x4.shared.b16 {%0,%1,%2,%3}, [%4];" \
        : "=r"(r0), "=r"(r1), "=r"(r2), "=r"(r3) : "r"(addr))
#define LDMATRIX_X4_TRANS(r0, r1, r2, r3, addr) \
    asm volatile("ldmatrix.sync.aligned.m8n8.x4.trans.shared.b16 {%0,%1,%2,%3}, [%4];" \
        : "=r"(r0), "=r"(r1), "=r"(r2), "=r"(r3) : "r"(addr))

__device__ __forceinline__ void hmma32(float* c, const uint32_t* a, const uint32_t* b) {
    asm volatile(
        "mma.sync.aligned.m16n8k16.row.col.f32.f16.f16.f32 "
        "{%0,%1,%2,%3}, {%4,%5,%6,%7}, {%8,%9}, {%0,%1,%2,%3};"
        : "+f"(c[0]), "+f"(c[1]), "+f"(c[2]), "+f"(c[3])
        : "r"(a[0]), "r"(a[1]), "r"(a[2]), "r"(a[3]), "r"(b[0]), "r"(b[1]));
}

__device__ __forceinline__ uint32_t pack_f2h2(float a, float b) {
    __half2 t; t.x = __float2half_rn(a); t.y = __float2half_rn(b);
    return *(uint32_t*)&t;
}

// ---------------- LayerNorm -> fp16 ------------------------------------------
__global__ __launch_bounds__(256)
void ln_kernel(const float* __restrict__ x, const float* __restrict__ w,
               const float* __restrict__ b, __half* __restrict__ o) {
    int row = blockIdx.x;
    const float4* xr = (const float4*)(x + (size_t)row * D_MODEL);
    float4 v = xr[threadIdx.x];
    float s  = v.x + v.y + v.z + v.w;
    float ss = v.x*v.x + v.y*v.y + v.z*v.z + v.w*v.w;
    #pragma unroll
    for (int of = 16; of; of >>= 1) {
        s  += __shfl_down_sync(0xffffffffu, s,  of);
        ss += __shfl_down_sync(0xffffffffu, ss, of);
    }
    __shared__ float rs[8], rss[8];
    __shared__ float mu_s, rstd_s;
    int wid = threadIdx.x >> 5, lid = threadIdx.x & 31;
    if (lid == 0) { rs[wid] = s; rss[wid] = ss; }
    __syncthreads();
    if (threadIdx.x == 0) {
        float ts = 0.f, tss = 0.f;
        #pragma unroll
        for (int i = 0; i < 8; i++) { ts += rs[i]; tss += rss[i]; }
        float mu  = ts * (1.0f / D_MODEL);
        float var = tss * (1.0f / D_MODEL) - mu * mu;
        mu_s = mu; rstd_s = rsqrtf(var + 1e-5f);
    }
    __syncthreads();
    float mu = mu_s, rstd = rstd_s;
    float4 wv = ((const float4*)w)[threadIdx.x];
    float4 bv = ((const float4*)b)[threadIdx.x];
    float o0 = (v.x - mu) * rstd * wv.x + bv.x;
    float o1 = (v.y - mu) * rstd * wv.y + bv.y;
    float o2 = (v.z - mu) * rstd * wv.z + bv.z;
    float o3 = (v.w - mu) * rstd * wv.w + bv.w;
    uint2 pk;
    pk.x = pack_f2h2(o0, o1);
    pk.y = pack_f2h2(o2, o3);
    *(uint2*)(o + (size_t)row * D_MODEL + threadIdx.x * 4) = pk;
}

// ---------------- weight transpose: W[K,N] -> Wt[N,K] fp16 -------------------
__global__ __launch_bounds__(256)
void wtrans_kernel(const float* __restrict__ W, __half* __restrict__ wt,
                   int K, int N) {
    __shared__ float t[32][33];
    int n0 = blockIdx.x * 32, k0 = blockIdx.y * 32;
    int tx = threadIdx.x & 31, ty = threadIdx.x >> 5;
    #pragma unroll
    for (int i = 0; i < 32; i += 8)
        t[ty + i][tx] = W[(size_t)(k0 + ty + i) * N + n0 + tx];
    __syncthreads();
    #pragma unroll
    for (int i = 0; i < 32; i += 8) {
        float v = t[tx][ty + i];
        wt[(size_t)(n0 + ty + i) * K + k0 + tx] = __float2half_rn(v);
    }
}

// ---------------- fp16 HMMA GEMM: C = A @ B^T --------------------------------
// CTA tile 128x128, BK=64 (SW128), 3-stage cp.async ring, 2 CTAs/SM.
// EPI: 0 bias -> f32 C; 1 bias+residual -> f32 C; 2 bias+GELU -> f16; 3 bias -> f16
#define GEMM_STAGE_BYTES 32768           // A 16K | B 16K
#define GEMM_NSTAGE 3
#define GEMM_SMEM_BYTES (GEMM_NSTAGE * GEMM_STAGE_BYTES)

template<int EPI>
__global__ __launch_bounds__(256, 2)
void gemm_tc(const __half* __restrict__ A, const __half* __restrict__ B,
             const float* __restrict__ bias, const float* __restrict__ res,
             float* __restrict__ C, __half* __restrict__ Ch,
             int M, int N, int K) {
    extern __shared__ __align__(128) char smem[];
    uint32_t su = smem_to_u32(smem);

    const int tid  = threadIdx.x;
    const int lane = tid & 31;
    const int wid  = tid >> 5;
    const int wm   = (wid & 1) * 64;    // 2 warps along M
    const int wn   = (wid >> 1) * 32;   // 4 warps along N
    const int m0 = blockIdx.y * 128, n0 = blockIdx.x * 128;

    float acc[4][4][4];
    #pragma unroll
    for (int i = 0; i < 4; i++)
        #pragma unroll
        for (int j = 0; j < 4; j++)
            #pragma unroll
            for (int k = 0; k < 4; k++) acc[i][j][k] = 0.f;

    const int nkt = K >> 6;              // K / 64
    const int lrow16 = lane & 15;
    const int khalf  = (lane >> 4) << 4; // 0 / 16 bytes

    int lr[4];
    int lc[4];
    uint32_t ld[4];
    #pragma unroll
    for (int j = 0; j < 4; j++) {
        int e = j * 256 + tid;
        lr[j] = e >> 3;
        lc[j] = e & 7;
        ld[j] = SMEM_SWIZZLE_128B((uint32_t)(lr[j] * 128 + lc[j] * 16));
    }

    auto issue_loads = [&](int kt) {
        uint32_t base = su + (kt % GEMM_NSTAGE) * GEMM_STAGE_BYTES;
        int k0 = kt << 6;
        #pragma unroll
        for (int j = 0; j < 4; j++) {
            size_t a0 = (size_t)(m0 + lr[j]) * K + k0 + lc[j] * 8;
            size_t b0 = (size_t)(n0 + lr[j]) * K + k0 + lc[j] * 8;
            CP_ASYNC16(base +         ld[j], A + a0);
            CP_ASYNC16(base + 16384 + ld[j], B + b0);
        }
        CP_COMMIT();
    };

    issue_loads(0);
    if (nkt > 1) issue_loads(1);

    for (int kt = 0; kt < nkt; kt++) {
        if (kt + 1 < nkt) { CP_WAIT1(); } else { CP_WAIT0(); }
        __syncthreads();
        if (kt + 2 < nkt) issue_loads(kt + 2);

        uint32_t base = su + (kt % GEMM_NSTAGE) * GEMM_STAGE_BYTES;
        #pragma unroll
        for (int ks = 0; ks < 4; ks++) {
            const uint32_t kb = (uint32_t)(ks * 32 + khalf);
            uint32_t bh[4][2];
            #pragma unroll
            for (int p = 0; p < 2; p++) {
                int r = wn + p * 16 + lrow16;
                uint32_t off = (uint32_t)(r * 128) + (kb ^ (uint32_t)((r & 7) << 4));
                uint32_t t0, t1, t2, t3;
                LDMATRIX_X4(t0, t1, t2, t3, base + 16384 + off);
                bh[p*2][0] = t0; bh[p*2][1] = t2;
                bh[p*2+1][0] = t1; bh[p*2+1][1] = t3;
            }
            #pragma unroll
            for (int mt = 0; mt < 4; mt++) {
                int r = wm + mt * 16 + lrow16;
                uint32_t off = (uint32_t)(r * 128) + (kb ^ (uint32_t)((r & 7) << 4));
                uint32_t ah[4];
                LDMATRIX_X4(ah[0], ah[1], ah[2], ah[3], base + off);
                #pragma unroll
                for (int nt = 0; nt < 4; nt++)
                    hmma32(acc[mt][nt], ah, bh[nt]);
            }
        }
    }

    const int rbase = m0 + wm + (lane >> 2);
    const int cbase = n0 + wn + (lane & 3) * 2;
    #pragma unroll
    for (int mt = 0; mt < 4; mt++) {
        #pragma unroll
        for (int nt = 0; nt < 4; nt++) {
            int col = cbase + nt * 8;
            float b0 = bias[col], b1 = bias[col + 1];
            #pragma unroll
            for (int half = 0; half < 2; half++) {
                int row = rbase + mt * 16 + half * 8;
                float v0 = acc[mt][nt][half * 2]     + b0;
                float v1 = acc[mt][nt][half * 2 + 1] + b1;
                if (EPI == 1) {
                    float2 rv = *(const float2*)(res + (size_t)row * N + col);
                    v0 += rv.x; v1 += rv.y;
                }
                if (EPI == 2) {
                    v0 = 0.5f * v0 * (1.0f + erff(v0 * 0.70710678118654752f));
                    v1 = 0.5f * v1 * (1.0f + erff(v1 * 0.70710678118654752f));
                }
                if (EPI >= 2) {
                    *(uint32_t*)(Ch + (size_t)row * N + col) = pack_f2h2(v0, v1);
                } else {
                    float2 o; o.x = v0; o.y = v1;
                    *(float2*)(C + (size_t)row * N + col) = o;
                }
            }
        }
    }
}

// ---------------- tensor-core flash attention --------------------------------
// 256 threads = 8 warps; q-tile 256, each warp owns 32 q rows (2 m-subtiles).
// KV tiles of 128 (Bc=128), double buffered. Pure fp16 operands, fp32 acc.
#define ATTN_SMEM (32768 + 2 * 32768)   // Q 32K + 2 KV stages (K 16K + V 16K)

__global__ __launch_bounds__(256)
void attn_tc(const __half* __restrict__ qkv, __half* __restrict__ y) {
    extern __shared__ __align__(128) char smem[];
    uint32_t su = smem_to_u32(smem);
    const int tid = threadIdx.x, lane = tid & 31, w = tid >> 5;  // 8 warps
    const int bh = blockIdx.y, b = bh >> 4, h = bh & 15;
    const int qt = (int)gridDim.x - 1 - (int)blockIdx.x;   // big tiles first
    const int ntiles = qt * 2 + 2;

    const uint32_t QH = su;
    const size_t qrow0 = (size_t)(b * TT + qt * 256);

    // Q tile: 256 rows x 64 cols fp16 (128B rows), SW128
    #pragma unroll
    for (int j = 0; j < 8; j++) {
        int e = j * 256 + tid; int r = e >> 3, c = e & 7;
        uint32_t d = SMEM_SWIZZLE_128B((uint32_t)(r * 128 + c * 16));
        CP_ASYNC16(QH + d, qkv + (qrow0 + r) * (3 * D_MODEL) + h * 64 + c * 8);
    }
    auto issue_kv = [&](int kt, int s) {
        uint32_t base = su + 32768 + s * 32768;
        size_t krow0 = (size_t)(b * TT + kt * 128);
        #pragma unroll
        for (int j = 0; j < 4; j++) {
            int e = j * 256 + tid; int r = e >> 3, c = e & 7;
            uint32_t d = SMEM_SWIZZLE_128B((uint32_t)(r * 128 + c * 16));
            size_t ksrc = (krow0 + r) * (3 * D_MODEL) + D_MODEL + h * 64 + c * 8;
            CP_ASYNC16(base +         d, qkv + ksrc);
            CP_ASYNC16(base + 16384 + d, qkv + ksrc + D_MODEL);
        }
        CP_COMMIT();
    };
    issue_kv(0, 0);

    float O[2][8][4];
    #pragma unroll
    for (int mt = 0; mt < 2; mt++)
        #pragma unroll
        for (int dt = 0; dt < 8; dt++)
            #pragma unroll
            for (int k = 0; k < 4; k++) O[mt][dt][k] = 0.f;
    float mrow[2][2] = {{-1e30f, -1e30f}, {-1e30f, -1e30f}};
    float lrow[2][2] = {{0.f, 0.f}, {0.f, 0.f}};

    const int lrow16 = lane & 15;
    const uint32_t khalfB = (uint32_t)((lane >> 4) << 4);
    const int r4 = lane >> 2, c2 = (lane & 3) * 2;

    for (int kt = 0; kt < ntiles; kt++) {
        int s = kt & 1;
        if (kt + 1 < ntiles) { issue_kv(kt + 1, s ^ 1); CP_WAIT1(); }
        else                 { CP_WAIT0(); }
        __syncthreads();
        const uint32_t KB = su + 32768 + s * 32768;
        const uint32_t VB = KB + 16384;

        #pragma unroll
        for (int mt = 0; mt < 2; mt++) {
            const int qmt = qt * 256 + w * 32 + mt * 16;
            const int q0  = qmt + r4;

            // ---- S = Q K^T : 16 q rows x 128 kv cols ----
            float sa[16][4];
            #pragma unroll
            for (int nt = 0; nt < 16; nt++)
                #pragma unroll
                for (int k = 0; k < 4; k++) sa[nt][k] = 0.f;

            #pragma unroll
            for (int ks = 0; ks < 4; ks++) {
                const uint32_t kb = (uint32_t)(ks * 32) + khalfB;
                const int ar = w * 32 + mt * 16 + lrow16;
                uint32_t aoff = (uint32_t)(ar * 128) + (kb ^ (uint32_t)((ar & 7) << 4));
                uint32_t ah[4];
                LDMATRIX_X4(ah[0], ah[1], ah[2], ah[3], QH + aoff);
                uint32_t kh[16][2];
                #pragma unroll
                for (int p = 0; p < 8; p++) {
                    const int br = p * 16 + lrow16;
                    uint32_t boff = (uint32_t)(br * 128) + (kb ^ (uint32_t)((br & 7) << 4));
                    uint32_t t0, t1, t2, t3;
                    LDMATRIX_X4(t0, t1, t2, t3, KB + boff);
                    kh[p*2][0] = t0; kh[p*2][1] = t2;
                    kh[p*2+1][0] = t1; kh[p*2+1][1] = t3;
                }
                #pragma unroll
                for (int nt = 0; nt < 16; nt++)
                    hmma32(sa[nt], ah, kh[nt]);
            }

            #pragma unroll
            for (int nt = 0; nt < 16; nt++)
                #pragma unroll
                for (int k = 0; k < 4; k++) sa[nt][k] *= 0.125f;

            // ---- causal mask (tiles overlapping this warp's rows) ----
            if (kt * 128 + 127 > qmt) {
                #pragma unroll
                for (int nt = 0; nt < 16; nt++) {
                    int kv0 = kt * 128 + nt * 8 + c2;
                    if (kv0     > q0)     sa[nt][0] = -1e30f;
                    if (kv0 + 1 > q0)     sa[nt][1] = -1e30f;
                    if (kv0     > q0 + 8) sa[nt][2] = -1e30f;
                    if (kv0 + 1 > q0 + 8) sa[nt][3] = -1e30f;
                }
            }

            // ---- online softmax ----
            float tm0 = -1e30f, tm1 = -1e30f;
            #pragma unroll
            for (int nt = 0; nt < 16; nt++) {
                tm0 = fmaxf(tm0, fmaxf(sa[nt][0], sa[nt][1]));
                tm1 = fmaxf(tm1, fmaxf(sa[nt][2], sa[nt][3]));
            }
            tm0 = fmaxf(tm0, __shfl_xor_sync(0xffffffffu, tm0, 1));
            tm0 = fmaxf(tm0, __shfl_xor_sync(0xffffffffu, tm0, 2));
            tm1 = fmaxf(tm1, __shfl_xor_sync(0xffffffffu, tm1, 1));
            tm1 = fmaxf(tm1, __shfl_xor_sync(0xffffffffu, tm1, 2));
            float nm0 = fmaxf(mrow[mt][0], tm0), nm1 = fmaxf(mrow[mt][1], tm1);
            float cor0 = __expf(mrow[mt][0] - nm0), cor1 = __expf(mrow[mt][1] - nm1);
            mrow[mt][0] = nm0; mrow[mt][1] = nm1;

            float ps0 = 0.f, ps1 = 0.f;
            uint32_t Ph[16][2];
            #pragma unroll
            for (int nt = 0; nt < 16; nt++) {
                float p00 = __expf(sa[nt][0] - nm0), p01 = __expf(sa[nt][1] - nm0);
                float p10 = __expf(sa[nt][2] - nm1), p11 = __expf(sa[nt][3] - nm1);
                ps0 += p00 + p01; ps1 += p10 + p11;
                Ph[nt][0] = pack_f2h2(p00, p01);
                Ph[nt][1] = pack_f2h2(p10, p11);
            }
            ps0 += __shfl_xor_sync(0xffffffffu, ps0, 1);
            ps0 += __shfl_xor_sync(0xffffffffu, ps0, 2);
            ps1 += __shfl_xor_sync(0xffffffffu, ps1, 1);
            ps1 += __shfl_xor_sync(0xffffffffu, ps1, 2);
            lrow[mt][0] = lrow[mt][0] * cor0 + ps0;
            lrow[mt][1] = lrow[mt][1] * cor1 + ps1;

            #pragma unroll
            for (int dt = 0; dt < 8; dt++) {
                O[mt][dt][0] *= cor0; O[mt][dt][1] *= cor0;
                O[mt][dt][2] *= cor1; O[mt][dt][3] *= cor1;
            }

            // ---- O += P V : P 16x128, V 128x64 ----
            #pragma unroll
            for (int ks = 0; ks < 8; ks++) {
                uint32_t vh[8][2];
                #pragma unroll
                for (int dc = 0; dc < 4; dc++) {
                    const int vr = ks * 16 + lrow16;
                    uint32_t voff = (uint32_t)(vr * 128) +
                        (((uint32_t)(dc * 32) + khalfB) ^ (uint32_t)((vr & 7) << 4));
                    uint32_t t0, t1, t2, t3;
                    LDMATRIX_X4_TRANS(t0, t1, t2, t3, VB + voff);
                    vh[dc*2][0] = t0; vh[dc*2][1] = t1;
                    vh[dc*2+1][0] = t2; vh[dc*2+1][1] = t3;
                }
                uint32_t aph[4] = {Ph[2*ks][0], Ph[2*ks][1], Ph[2*ks+1][0], Ph[2*ks+1][1]};
                #pragma unroll
                for (int dt = 0; dt < 8; dt++)
                    hmma32(O[mt][dt], aph, vh[dt]);
            }
        } // mt
        __syncthreads();
    } // kt

    #pragma unroll
    for (int mt = 0; mt < 2; mt++) {
        float inv0 = 1.0f / lrow[mt][0], inv1 = 1.0f / lrow[mt][1];
        size_t row0 = qrow0 + w * 32 + mt * 16 + r4;
        size_t row1 = row0 + 8;
        #pragma unroll
        for (int dt = 0; dt < 8; dt++) {
            int col = h * 64 + dt * 8 + c2;
            *(uint32_t*)(y + row0 * D_MODEL + col) =
                pack_f2h2(O[mt][dt][0] * inv0, O[mt][dt][1] * inv0);
            *(uint32_t*)(y + row1 * D_MODEL + col) =
                pack_f2h2(O[mt][dt][2] * inv1, O[mt][dt][3] * inv1);
        }
    }
}

// ---------------- streams/events (created pre-main, outside mem checkpoints) -
struct GraphForks {
    cudaStream_t s1;
    cudaEvent_t fork, evA, evB, evC, evD;
    GraphForks() {
        cudaStreamCreateWithFlags(&s1, cudaStreamNonBlocking);
        cudaEventCreateWithFlags(&fork, cudaEventDisableTiming);
        cudaEventCreateWithFlags(&evA,  cudaEventDisableTiming);
        cudaEventCreateWithFlags(&evB,  cudaEventDisableTiming);
        cudaEventCreateWithFlags(&evC,  cudaEventDisableTiming);
        cudaEventCreateWithFlags(&evD,  cudaEventDisableTiming);
    }
};
static GraphForks g_forks;

// ---------------- launch ----------------------------------------------------
extern "C" void kernel_launch(void* const* d_in, const int* in_sizes, int n_in,
                              void* d_out, int out_size) {
    const float* x      = (const float*)d_in[0];
    const float* ln1_w  = (const float*)d_in[1];
    const float* ln1_b  = (const float*)d_in[2];
    const float* attn_w = (const float*)d_in[3];
    const float* attn_b = (const float*)d_in[4];
    const float* proj_w = (const float*)d_in[5];
    const float* proj_b = (const float*)d_in[6];
    const float* ln2_w  = (const float*)d_in[7];
    const float* ln2_b  = (const float*)d_in[8];
    const float* fc_w   = (const float*)d_in[9];
    const float* fc_b   = (const float*)d_in[10];
    const float* fc2_w  = (const float*)d_in[11];
    const float* fc2_b  = (const float*)d_in[12];
    float* out = (float*)d_out;

    __half *a, *hh, *w0, *w1, *w2, *w3;
    float *x1;
    cudaGetSymbolAddress((void**)&a,  g_a);
    cudaGetSymbolAddress((void**)&hh, g_h);
    cudaGetSymbolAddress((void**)&w0, g_w0);
    cudaGetSymbolAddress((void**)&w1, g_w1);
    cudaGetSymbolAddress((void**)&w2, g_w2);
    cudaGetSymbolAddress((void**)&w3, g_w3);
    cudaGetSymbolAddress((void**)&x1, g_x1);

    static bool attr_set = false;
    if (!attr_set) {
        cudaFuncSetAttribute(gemm_tc<0>, cudaFuncAttributeMaxDynamicSharedMemorySize, GEMM_SMEM_BYTES);
        cudaFuncSetAttribute(gemm_tc<1>, cudaFuncAttributeMaxDynamicSharedMemorySize, GEMM_SMEM_BYTES);
        cudaFuncSetAttribute(gemm_tc<2>, cudaFuncAttributeMaxDynamicSharedMemorySize, GEMM_SMEM_BYTES);
        cudaFuncSetAttribute(gemm_tc<3>, cudaFuncAttributeMaxDynamicSharedMemorySize, GEMM_SMEM_BYTES);
        cudaFuncSetAttribute(attn_tc,    cudaFuncAttributeMaxDynamicSharedMemorySize, ATTN_SMEM);
        attr_set = true;
    }

    cudaStream_t s0 = 0;
    cudaStream_t s1 = g_forks.s1;

    // Fork: weight transposes on s1 (fills launch-gap bubbles).
    cudaEventRecord(g_forks.fork, s0);
    cudaStreamWaitEvent(s1, g_forks.fork, 0);
    wtrans_kernel<<<dim3(3 * D_MODEL / 32, D_MODEL / 32), 256, 0, s1>>>(attn_w, w0, D_MODEL, 3 * D_MODEL);
    cudaEventRecord(g_forks.evA, s1);
    wtrans_kernel<<<dim3(D_MODEL / 32, D_MODEL / 32), 256, 0, s1>>>(proj_w, w1, D_MODEL, D_MODEL);
    cudaEventRecord(g_forks.evB, s1);
    wtrans_kernel<<<dim3(EXPAND * D_MODEL / 32, D_MODEL / 32), 256, 0, s1>>>(fc_w, w2, D_MODEL, EXPAND * D_MODEL);
    cudaEventRecord(g_forks.evC, s1);
    wtrans_kernel<<<dim3(D_MODEL / 32, EXPAND * D_MODEL / 32), 256, 0, s1>>>(fc2_w, w3, EXPAND * D_MODEL, D_MODEL);
    cudaEventRecord(g_forks.evD, s1);

    // Main chain on s0.
    ln_kernel<<<ROWS, 256, 0, s0>>>(x, ln1_w, ln1_b, a);
    cudaStreamWaitEvent(s0, g_forks.evA, 0);
    gemm_tc<3><<<dim3(3 * D_MODEL / 128, ROWS / 128), 256, GEMM_SMEM_BYTES, s0>>>(
        a, w0, attn_b, nullptr, nullptr, hh, ROWS, 3 * D_MODEL, D_MODEL);
    attn_tc<<<dim3(TT / 256, BB * N_HEAD), 256, ATTN_SMEM, s0>>>(hh, a);
    cudaStreamWaitEvent(s0, g_forks.evB, 0);
    gemm_tc<1><<<dim3(D_MODEL / 128, ROWS / 128), 256, GEMM_SMEM_BYTES, s0>>>(
        a, w1, proj_b, x, x1, nullptr, ROWS, D_MODEL, D_MODEL);
    ln_kernel<<<ROWS, 256, 0, s0>>>(x1, ln2_w, ln2_b, a);
    cudaStreamWaitEvent(s0, g_forks.evC, 0);
    gemm_tc<2><<<dim3(EXPAND * D_MODEL / 128, ROWS / 128), 256, GEMM_SMEM_BYTES, s0>>>(
        a, w2, fc_b, nullptr, nullptr, hh, ROWS, EXPAND * D_MODEL, D_MODEL);
    cudaStreamWaitEvent(s0, g_forks.evD, 0);
    gemm_tc<1><<<dim3(D_MODEL / 128, ROWS / 128), 256, GEMM_SMEM_BYTES, s0>>>(
        hh, w3, fc2_b, x1, out, nullptr, ROWS, D_MODEL, EXPAND * D_MODEL);
}

// round 16
// speedup vs baseline: 1.0450x; 1.0450x over previous
#include <cuda_runtime.h>
#include <cuda_fp16.h>
#include <math.h>
#include <stdint.h>

#define D_MODEL 1024
#define N_HEAD  16
#define BB      2
#define TT      2048
#define ROWS    (BB*TT)      // 4096
#define EXPAND  4

// ---------------- scratch (device globals; no allocation allowed) ----------
__device__ __half g_a  [ROWS * D_MODEL];            // activations (ln1/y/ln2)
__device__ __half g_h  [ROWS * EXPAND * D_MODEL];   // qkv (3C) / mlp hidden (4C)
__device__ __half g_w0 [3 * D_MODEL * D_MODEL];     // attn_w^T
__device__ __half g_w1 [D_MODEL * D_MODEL];         // proj_w^T
__device__ __half g_w2 [EXPAND * D_MODEL * D_MODEL];// fc_w^T
__device__ __half g_w3 [EXPAND * D_MODEL * D_MODEL];// fc2_w^T
__device__ float  g_x1 [ROWS * D_MODEL];

// ================= helpers ==================================================
__device__ __forceinline__ uint32_t smem_to_u32(const void* p) {
    uint32_t a;
    asm("{ .reg .u64 t; cvta.to.shared.u64 t, %1; cvt.u32.u64 %0, t; }" : "=r"(a) : "l"(p));
    return a;
}
#define SMEM_SWIZZLE_128B(off) ((off) ^ (((off) >> 3) & 0x70))

#define CP_ASYNC16(dst_u32, src_ptr) \
    asm volatile("cp.async.cg.shared.global [%0], [%1], 16;" :: "r"(dst_u32), "l"(src_ptr))
#define CP_COMMIT() asm volatile("cp.async.commit_group;" ::: "memory")
#define CP_WAIT0()  asm volatile("cp.async.wait_group 0;" ::: "memory")
#define CP_WAIT1()  asm volatile("cp.async.wait_group 1;" ::: "memory")

#define LDMATRIX_X4(r0, r1, r2, r3, addr) \
    asm volatile("ldmatrix.sync.aligned.m8n8.x4.shared.b16 {%0,%1,%2,%3}, [%4];" \
        : "=r"(r0), "=r"(r1), "=r"(r2), "=r"(r3) : "r"(addr))
#define LDMATRIX_X4_TRANS(r0, r1, r2, r3, addr) \
    asm volatile("ldmatrix.sync.aligned.m8n8.x4.trans.shared.b16 {%0,%1,%2,%3}, [%4];" \
        : "=r"(r0), "=r"(r1), "=r"(r2), "=r"(r3) : "r"(addr))

__device__ __forceinline__ void hmma32(float* c, const uint32_t* a, const uint32_t* b) {
    asm volatile(
        "mma.sync.aligned.m16n8k16.row.col.f32.f16.f16.f32 "
        "{%0,%1,%2,%3}, {%4,%5,%6,%7}, {%8,%9}, {%0,%1,%2,%3};"
        : "+f"(c[0]), "+f"(c[1]), "+f"(c[2]), "+f"(c[3])
        : "r"(a[0]), "r"(a[1]), "r"(a[2]), "r"(a[3]), "r"(b[0]), "r"(b[1]));
}

__device__ __forceinline__ uint32_t pack_f2h2(float a, float b) {
    __half2 t; t.x = __float2half_rn(a); t.y = __float2half_rn(b);
    return *(uint32_t*)&t;
}

// ---------------- LayerNorm -> fp16 ------------------------------------------
__global__ __launch_bounds__(256)
void ln_kernel(const float* __restrict__ x, const float* __restrict__ w,
               const float* __restrict__ b, __half* __restrict__ o) {
    int row = blockIdx.x;
    const float4* xr = (const float4*)(x + (size_t)row * D_MODEL);
    float4 v = xr[threadIdx.x];
    float s  = v.x + v.y + v.z + v.w;
    float ss = v.x*v.x + v.y*v.y + v.z*v.z + v.w*v.w;
    #pragma unroll
    for (int of = 16; of; of >>= 1) {
        s  += __shfl_down_sync(0xffffffffu, s,  of);
        ss += __shfl_down_sync(0xffffffffu, ss, of);
    }
    __shared__ float rs[8], rss[8];
    __shared__ float mu_s, rstd_s;
    int wid = threadIdx.x >> 5, lid = threadIdx.x & 31;
    if (lid == 0) { rs[wid] = s; rss[wid] = ss; }
    __syncthreads();
    if (threadIdx.x == 0) {
        float ts = 0.f, tss = 0.f;
        #pragma unroll
        for (int i = 0; i < 8; i++) { ts += rs[i]; tss += rss[i]; }
        float mu  = ts * (1.0f / D_MODEL);
        float var = tss * (1.0f / D_MODEL) - mu * mu;
        mu_s = mu; rstd_s = rsqrtf(var + 1e-5f);
    }
    __syncthreads();
    float mu = mu_s, rstd = rstd_s;
    float4 wv = ((const float4*)w)[threadIdx.x];
    float4 bv = ((const float4*)b)[threadIdx.x];
    float o0 = (v.x - mu) * rstd * wv.x + bv.x;
    float o1 = (v.y - mu) * rstd * wv.y + bv.y;
    float o2 = (v.z - mu) * rstd * wv.z + bv.z;
    float o3 = (v.w - mu) * rstd * wv.w + bv.w;
    uint2 pk;
    pk.x = pack_f2h2(o0, o1);
    pk.y = pack_f2h2(o2, o3);
    *(uint2*)(o + (size_t)row * D_MODEL + threadIdx.x * 4) = pk;
}

// ---------------- weight transpose: W[K,N] -> Wt[N,K] fp16 -------------------
__global__ __launch_bounds__(256)
void wtrans_kernel(const float* __restrict__ W, __half* __restrict__ wt,
                   int K, int N) {
    __shared__ float t[32][33];
    int n0 = blockIdx.x * 32, k0 = blockIdx.y * 32;
    int tx = threadIdx.x & 31, ty = threadIdx.x >> 5;
    #pragma unroll
    for (int i = 0; i < 32; i += 8)
        t[ty + i][tx] = W[(size_t)(k0 + ty + i) * N + n0 + tx];
    __syncthreads();
    #pragma unroll
    for (int i = 0; i < 32; i += 8) {
        float v = t[tx][ty + i];
        wt[(size_t)(n0 + ty + i) * K + k0 + tx] = __float2half_rn(v);
    }
}

// ---------------- fp16 HMMA GEMM: C = A @ B^T --------------------------------
// CTA tile 128x128, BK=64 (SW128), 3-stage cp.async ring, 2 CTAs/SM.
// EPI: 0 bias -> f32 C; 1 bias+residual -> f32 C; 2 bias+GELU -> f16; 3 bias -> f16
#define GEMM_STAGE_BYTES 32768           // A 16K | B 16K
#define GEMM_NSTAGE 3
#define GEMM_SMEM_BYTES (GEMM_NSTAGE * GEMM_STAGE_BYTES)

template<int EPI>
__global__ __launch_bounds__(256, 2)
void gemm_tc(const __half* __restrict__ A, const __half* __restrict__ B,
             const float* __restrict__ bias, const float* __restrict__ res,
             float* __restrict__ C, __half* __restrict__ Ch,
             int M, int N, int K) {
    extern __shared__ __align__(128) char smem[];
    uint32_t su = smem_to_u32(smem);

    const int tid  = threadIdx.x;
    const int lane = tid & 31;
    const int wid  = tid >> 5;
    const int wm   = (wid & 1) * 64;    // 2 warps along M
    const int wn   = (wid >> 1) * 32;   // 4 warps along N
    const int m0 = blockIdx.y * 128, n0 = blockIdx.x * 128;

    float acc[4][4][4];
    #pragma unroll
    for (int i = 0; i < 4; i++)
        #pragma unroll
        for (int j = 0; j < 4; j++)
            #pragma unroll
            for (int k = 0; k < 4; k++) acc[i][j][k] = 0.f;

    const int nkt = K >> 6;              // K / 64
    const int lrow16 = lane & 15;
    const int khalf  = (lane >> 4) << 4; // 0 / 16 bytes

    int lr[4];
    int lc[4];
    uint32_t ld[4];
    #pragma unroll
    for (int j = 0; j < 4; j++) {
        int e = j * 256 + tid;
        lr[j] = e >> 3;
        lc[j] = e & 7;
        ld[j] = SMEM_SWIZZLE_128B((uint32_t)(lr[j] * 128 + lc[j] * 16));
    }

    auto issue_loads = [&](int kt) {
        uint32_t base = su + (kt % GEMM_NSTAGE) * GEMM_STAGE_BYTES;
        int k0 = kt << 6;
        #pragma unroll
        for (int j = 0; j < 4; j++) {
            size_t a0 = (size_t)(m0 + lr[j]) * K + k0 + lc[j] * 8;
            size_t b0 = (size_t)(n0 + lr[j]) * K + k0 + lc[j] * 8;
            CP_ASYNC16(base +         ld[j], A + a0);
            CP_ASYNC16(base + 16384 + ld[j], B + b0);
        }
        CP_COMMIT();
    };

    issue_loads(0);
    if (nkt > 1) issue_loads(1);

    for (int kt = 0; kt < nkt; kt++) {
        if (kt + 1 < nkt) { CP_WAIT1(); } else { CP_WAIT0(); }
        __syncthreads();
        if (kt + 2 < nkt) issue_loads(kt + 2);

        uint32_t base = su + (kt % GEMM_NSTAGE) * GEMM_STAGE_BYTES;
        #pragma unroll
        for (int ks = 0; ks < 4; ks++) {
            const uint32_t kb = (uint32_t)(ks * 32 + khalf);
            uint32_t bh[4][2];
            #pragma unroll
            for (int p = 0; p < 2; p++) {
                int r = wn + p * 16 + lrow16;
                uint32_t off = (uint32_t)(r * 128) + (kb ^ (uint32_t)((r & 7) << 4));
                uint32_t t0, t1, t2, t3;
                LDMATRIX_X4(t0, t1, t2, t3, base + 16384 + off);
                bh[p*2][0] = t0; bh[p*2][1] = t2;
                bh[p*2+1][0] = t1; bh[p*2+1][1] = t3;
            }
            #pragma unroll
            for (int mt = 0; mt < 4; mt++) {
                int r = wm + mt * 16 + lrow16;
                uint32_t off = (uint32_t)(r * 128) + (kb ^ (uint32_t)((r & 7) << 4));
                uint32_t ah[4];
                LDMATRIX_X4(ah[0], ah[1], ah[2], ah[3], base + off);
                #pragma unroll
                for (int nt = 0; nt < 4; nt++)
                    hmma32(acc[mt][nt], ah, bh[nt]);
            }
        }
    }

    const int rbase = m0 + wm + (lane >> 2);
    const int cbase = n0 + wn + (lane & 3) * 2;
    #pragma unroll
    for (int mt = 0; mt < 4; mt++) {
        #pragma unroll
        for (int nt = 0; nt < 4; nt++) {
            int col = cbase + nt * 8;
            float b0 = bias[col], b1 = bias[col + 1];
            #pragma unroll
            for (int half = 0; half < 2; half++) {
                int row = rbase + mt * 16 + half * 8;
                float v0 = acc[mt][nt][half * 2]     + b0;
                float v1 = acc[mt][nt][half * 2 + 1] + b1;
                if (EPI == 1) {
                    float2 rv = *(const float2*)(res + (size_t)row * N + col);
                    v0 += rv.x; v1 += rv.y;
                }
                if (EPI == 2) {
                    v0 = 0.5f * v0 * (1.0f + erff(v0 * 0.70710678118654752f));
                    v1 = 0.5f * v1 * (1.0f + erff(v1 * 0.70710678118654752f));
                }
                if (EPI >= 2) {
                    *(uint32_t*)(Ch + (size_t)row * N + col) = pack_f2h2(v0, v1);
                } else {
                    float2 o; o.x = v0; o.y = v1;
                    *(float2*)(C + (size_t)row * N + col) = o;
                }
            }
        }
    }
}

// ---------------- tensor-core flash attention --------------------------------
// 256 threads = 8 warps; each warp owns one 16-row q block (q-tile = 128).
// KV tiles of 128 (Bc=128), double buffered. Pure fp16 operands, fp32 acc.
#define ATTN_SMEM (16384 + 2 * 32768)   // Q 16K + 2 KV stages (K 16K + V 16K)

__global__ __launch_bounds__(256)
void attn_tc(const __half* __restrict__ qkv, __half* __restrict__ y) {
    extern __shared__ __align__(128) char smem[];
    uint32_t su = smem_to_u32(smem);
    const int tid = threadIdx.x, lane = tid & 31, w = tid >> 5;  // 8 warps
    const int bh = blockIdx.y, b = bh >> 4, h = bh & 15;
    const int qt = (int)gridDim.x - 1 - (int)blockIdx.x;   // big tiles first
    const int ntiles = qt + 1;

    const uint32_t QH = su;
    const size_t qrow0 = (size_t)(b * TT + qt * 128);

    // Q tile: 128 rows x 64 cols fp16 (128B rows), SW128
    #pragma unroll
    for (int j = 0; j < 4; j++) {
        int e = j * 256 + tid; int r = e >> 3, c = e & 7;
        uint32_t d = SMEM_SWIZZLE_128B((uint32_t)(r * 128 + c * 16));
        CP_ASYNC16(QH + d, qkv + (qrow0 + r) * (3 * D_MODEL) + h * 64 + c * 8);
    }
    auto issue_kv = [&](int kt, int s) {
        uint32_t base = su + 16384 + s * 32768;
        size_t krow0 = (size_t)(b * TT + kt * 128);
        #pragma unroll
        for (int j = 0; j < 4; j++) {
            int e = j * 256 + tid; int r = e >> 3, c = e & 7;
            uint32_t d = SMEM_SWIZZLE_128B((uint32_t)(r * 128 + c * 16));
            size_t ksrc = (krow0 + r) * (3 * D_MODEL) + D_MODEL + h * 64 + c * 8;
            CP_ASYNC16(base +         d, qkv + ksrc);
            CP_ASYNC16(base + 16384 + d, qkv + ksrc + D_MODEL);
        }
        CP_COMMIT();
    };
    issue_kv(0, 0);

    float O[8][4];
    #pragma unroll
    for (int dt = 0; dt < 8; dt++)
        #pragma unroll
        for (int k = 0; k < 4; k++) O[dt][k] = 0.f;
    float mrow0 = -1e30f, mrow1 = -1e30f;
    float lrow0 = 0.f, lrow1 = 0.f;

    const int lrow16 = lane & 15;
    const uint32_t khalfB = (uint32_t)((lane >> 4) << 4);
    const int r4 = lane >> 2, c2 = (lane & 3) * 2;
    const int qmt = qt * 128 + w * 16;          // first q row of this warp
    const int q0  = qmt + r4;                   // thread's first row

    for (int kt = 0; kt < ntiles; kt++) {
        int s = kt & 1;
        if (kt + 1 < ntiles) { issue_kv(kt + 1, s ^ 1); CP_WAIT1(); }
        else                 { CP_WAIT0(); }
        __syncthreads();
        const uint32_t KB = su + 16384 + s * 32768;
        const uint32_t VB = KB + 16384;

        // ---- S = Q K^T : 16 q rows x 128 kv cols ----
        float sa[16][4];
        #pragma unroll
        for (int nt = 0; nt < 16; nt++)
            #pragma unroll
            for (int k = 0; k < 4; k++) sa[nt][k] = 0.f;

        #pragma unroll
        for (int ks = 0; ks < 4; ks++) {
            const uint32_t kb = (uint32_t)(ks * 32) + khalfB;
            const int ar = w * 16 + lrow16;
            uint32_t aoff = (uint32_t)(ar * 128) + (kb ^ (uint32_t)((ar & 7) << 4));
            uint32_t ah[4];
            LDMATRIX_X4(ah[0], ah[1], ah[2], ah[3], QH + aoff);
            uint32_t kh[16][2];
            #pragma unroll
            for (int p = 0; p < 8; p++) {
                const int br = p * 16 + lrow16;
                uint32_t boff = (uint32_t)(br * 128) + (kb ^ (uint32_t)((br & 7) << 4));
                uint32_t t0, t1, t2, t3;
                LDMATRIX_X4(t0, t1, t2, t3, KB + boff);
                kh[p*2][0] = t0; kh[p*2][1] = t2;
                kh[p*2+1][0] = t1; kh[p*2+1][1] = t3;
            }
            #pragma unroll
            for (int nt = 0; nt < 16; nt++)
                hmma32(sa[nt], ah, kh[nt]);
        }

        #pragma unroll
        for (int nt = 0; nt < 16; nt++)
            #pragma unroll
            for (int k = 0; k < 4; k++) sa[nt][k] *= 0.125f;

        // ---- causal mask (only the diagonal tile) ----
        if (kt == qt) {
            #pragma unroll
            for (int nt = 0; nt < 16; nt++) {
                int kv0 = kt * 128 + nt * 8 + c2;
                if (kv0     > q0)     sa[nt][0] = -1e30f;
                if (kv0 + 1 > q0)     sa[nt][1] = -1e30f;
                if (kv0     > q0 + 8) sa[nt][2] = -1e30f;
                if (kv0 + 1 > q0 + 8) sa[nt][3] = -1e30f;
            }
        }

        // ---- online softmax ----
        float tm0 = -1e30f, tm1 = -1e30f;
        #pragma unroll
        for (int nt = 0; nt < 16; nt++) {
            tm0 = fmaxf(tm0, fmaxf(sa[nt][0], sa[nt][1]));
            tm1 = fmaxf(tm1, fmaxf(sa[nt][2], sa[nt][3]));
        }
        tm0 = fmaxf(tm0, __shfl_xor_sync(0xffffffffu, tm0, 1));
        tm0 = fmaxf(tm0, __shfl_xor_sync(0xffffffffu, tm0, 2));
        tm1 = fmaxf(tm1, __shfl_xor_sync(0xffffffffu, tm1, 1));
        tm1 = fmaxf(tm1, __shfl_xor_sync(0xffffffffu, tm1, 2));
        float nm0 = fmaxf(mrow0, tm0), nm1 = fmaxf(mrow1, tm1);
        float cor0 = __expf(mrow0 - nm0), cor1 = __expf(mrow1 - nm1);
        mrow0 = nm0; mrow1 = nm1;

        float ps0 = 0.f, ps1 = 0.f;
        uint32_t Ph[16][2];
        #pragma unroll
        for (int nt = 0; nt < 16; nt++) {
            float p00 = __expf(sa[nt][0] - nm0), p01 = __expf(sa[nt][1] - nm0);
            float p10 = __expf(sa[nt][2] - nm1), p11 = __expf(sa[nt][3] - nm1);
            ps0 += p00 + p01; ps1 += p10 + p11;
            Ph[nt][0] = pack_f2h2(p00, p01);
            Ph[nt][1] = pack_f2h2(p10, p11);
        }
        ps0 += __shfl_xor_sync(0xffffffffu, ps0, 1);
        ps0 += __shfl_xor_sync(0xffffffffu, ps0, 2);
        ps1 += __shfl_xor_sync(0xffffffffu, ps1, 1);
        ps1 += __shfl_xor_sync(0xffffffffu, ps1, 2);
        lrow0 = lrow0 * cor0 + ps0;
        lrow1 = lrow1 * cor1 + ps1;

        #pragma unroll
        for (int dt = 0; dt < 8; dt++) {
            O[dt][0] *= cor0; O[dt][1] *= cor0;
            O[dt][2] *= cor1; O[dt][3] *= cor1;
        }

        // ---- O += P V : P 16x128, V 128x64 ----
        #pragma unroll
        for (int ks = 0; ks < 8; ks++) {
            uint32_t vh[8][2];
            #pragma unroll
            for (int dc = 0; dc < 4; dc++) {
                const int vr = ks * 16 + lrow16;
                uint32_t voff = (uint32_t)(vr * 128) +
                    (((uint32_t)(dc * 32) + khalfB) ^ (uint32_t)((vr & 7) << 4));
                uint32_t t0, t1, t2, t3;
                LDMATRIX_X4_TRANS(t0, t1, t2, t3, VB + voff);
                vh[dc*2][0] = t0; vh[dc*2][1] = t1;
                vh[dc*2+1][0] = t2; vh[dc*2+1][1] = t3;
            }
            uint32_t aph[4] = {Ph[2*ks][0], Ph[2*ks][1], Ph[2*ks+1][0], Ph[2*ks+1][1]};
            #pragma unroll
            for (int dt = 0; dt < 8; dt++)
                hmma32(O[dt], aph, vh[dt]);
        }
        __syncthreads();
    } // kt

    float inv0 = 1.0f / lrow0, inv1 = 1.0f / lrow1;
    size_t row0 = qrow0 + w * 16 + r4;
    size_t row1 = row0 + 8;
    #pragma unroll
    for (int dt = 0; dt < 8; dt++) {
        int col = h * 64 + dt * 8 + c2;
        *(uint32_t*)(y + row0 * D_MODEL + col) = pack_f2h2(O[dt][0] * inv0, O[dt][1] * inv0);
        *(uint32_t*)(y + row1 * D_MODEL + col) = pack_f2h2(O[dt][2] * inv1, O[dt][3] * inv1);
    }
}

// ---------------- streams/events (created pre-main, outside mem checkpoints) -
struct GraphForks {
    cudaStream_t s1;
    cudaEvent_t fork, evA, evB, evC, evD;
    GraphForks() {
        cudaStreamCreateWithFlags(&s1, cudaStreamNonBlocking);
        cudaEventCreateWithFlags(&fork, cudaEventDisableTiming);
        cudaEventCreateWithFlags(&evA,  cudaEventDisableTiming);
        cudaEventCreateWithFlags(&evB,  cudaEventDisableTiming);
        cudaEventCreateWithFlags(&evC,  cudaEventDisableTiming);
        cudaEventCreateWithFlags(&evD,  cudaEventDisableTiming);
    }
};
static GraphForks g_forks;

// ---------------- launch ----------------------------------------------------
extern "C" void kernel_launch(void* const* d_in, const int* in_sizes, int n_in,
                              void* d_out, int out_size) {
    const float* x      = (const float*)d_in[0];
    const float* ln1_w  = (const float*)d_in[1];
    const float* ln1_b  = (const float*)d_in[2];
    const float* attn_w = (const float*)d_in[3];
    const float* attn_b = (const float*)d_in[4];
    const float* proj_w = (const float*)d_in[5];
    const float* proj_b = (const float*)d_in[6];
    const float* ln2_w  = (const float*)d_in[7];
    const float* ln2_b  = (const float*)d_in[8];
    const float* fc_w   = (const float*)d_in[9];
    const float* fc_b   = (const float*)d_in[10];
    const float* fc2_w  = (const float*)d_in[11];
    const float* fc2_b  = (const float*)d_in[12];
    float* out = (float*)d_out;

    __half *a, *hh, *w0, *w1, *w2, *w3;
    float *x1;
    cudaGetSymbolAddress((void**)&a,  g_a);
    cudaGetSymbolAddress((void**)&hh, g_h);
    cudaGetSymbolAddress((void**)&w0, g_w0);
    cudaGetSymbolAddress((void**)&w1, g_w1);
    cudaGetSymbolAddress((void**)&w2, g_w2);
    cudaGetSymbolAddress((void**)&w3, g_w3);
    cudaGetSymbolAddress((void**)&x1, g_x1);

    static bool attr_set = false;
    if (!attr_set) {
        cudaFuncSetAttribute(gemm_tc<0>, cudaFuncAttributeMaxDynamicSharedMemorySize, GEMM_SMEM_BYTES);
        cudaFuncSetAttribute(gemm_tc<1>, cudaFuncAttributeMaxDynamicSharedMemorySize, GEMM_SMEM_BYTES);
        cudaFuncSetAttribute(gemm_tc<2>, cudaFuncAttributeMaxDynamicSharedMemorySize, GEMM_SMEM_BYTES);
        cudaFuncSetAttribute(gemm_tc<3>, cudaFuncAttributeMaxDynamicSharedMemorySize, GEMM_SMEM_BYTES);
        cudaFuncSetAttribute(attn_tc,    cudaFuncAttributeMaxDynamicSharedMemorySize, ATTN_SMEM);
        attr_set = true;
    }

    cudaStream_t s0 = 0;
    cudaStream_t s1 = g_forks.s1;

    // Fork: weight transposes on s1 (fills launch-gap bubbles).
    cudaEventRecord(g_forks.fork, s0);
    cudaStreamWaitEvent(s1, g_forks.fork, 0);
    wtrans_kernel<<<dim3(3 * D_MODEL / 32, D_MODEL / 32), 256, 0, s1>>>(attn_w, w0, D_MODEL, 3 * D_MODEL);
    cudaEventRecord(g_forks.evA, s1);
    wtrans_kernel<<<dim3(D_MODEL / 32, D_MODEL / 32), 256, 0, s1>>>(proj_w, w1, D_MODEL, D_MODEL);
    cudaEventRecord(g_forks.evB, s1);
    wtrans_kernel<<<dim3(EXPAND * D_MODEL / 32, D_MODEL / 32), 256, 0, s1>>>(fc_w, w2, D_MODEL, EXPAND * D_MODEL);
    cudaEventRecord(g_forks.evC, s1);
    wtrans_kernel<<<dim3(D_MODEL / 32, EXPAND * D_MODEL / 32), 256, 0, s1>>>(fc2_w, w3, EXPAND * D_MODEL, D_MODEL);
    cudaEventRecord(g_forks.evD, s1);

    // Main chain on s0.
    ln_kernel<<<ROWS, 256, 0, s0>>>(x, ln1_w, ln1_b, a);
    cudaStreamWaitEvent(s0, g_forks.evA, 0);
    gemm_tc<3><<<dim3(3 * D_MODEL / 128, ROWS / 128), 256, GEMM_SMEM_BYTES, s0>>>(
        a, w0, attn_b, nullptr, nullptr, hh, ROWS, 3 * D_MODEL, D_MODEL);
    attn_tc<<<dim3(TT / 128, BB * N_HEAD), 256, ATTN_SMEM, s0>>>(hh, a);
    cudaStreamWaitEvent(s0, g_forks.evB, 0);
    gemm_tc<1><<<dim3(D_MODEL / 128, ROWS / 128), 256, GEMM_SMEM_BYTES, s0>>>(
        a, w1, proj_b, x, x1, nullptr, ROWS, D_MODEL, D_MODEL);
    ln_kernel<<<ROWS, 256, 0, s0>>>(x1, ln2_w, ln2_b, a);
    cudaStreamWaitEvent(s0, g_forks.evC, 0);
    gemm_tc<2><<<dim3(EXPAND * D_MODEL / 128, ROWS / 128), 256, GEMM_SMEM_BYTES, s0>>>(
        a, w2, fc_b, nullptr, nullptr, hh, ROWS, EXPAND * D_MODEL, D_MODEL);
    cudaStreamWaitEvent(s0, g_forks.evD, 0);
    gemm_tc<1><<<dim3(D_MODEL / 128, ROWS / 128), 256, GEMM_SMEM_BYTES, s0>>>(
        hh, w3, fc2_b, x1, out, nullptr, ROWS, D_MODEL, EXPAND * D_MODEL);
}

// round 17
// speedup vs baseline: 1.0492x; 1.0040x over previous
#include <cuda_runtime.h>
#include <cuda_fp16.h>
#include <math.h>
#include <stdint.h>

#define D_MODEL 1024
#define N_HEAD  16
#define BB      2
#define TT      2048
#define ROWS    (BB*TT)      // 4096
#define EXPAND  4

// ---------------- scratch (device globals; no allocation allowed) ----------
__device__ __half g_a  [ROWS * D_MODEL];            // activations (ln1/y/ln2)
__device__ __half g_h  [ROWS * EXPAND * D_MODEL];   // qkv (3C) / mlp hidden (4C)
__device__ __half g_w0 [3 * D_MODEL * D_MODEL];     // attn_w^T
__device__ __half g_w1 [D_MODEL * D_MODEL];         // proj_w^T
__device__ __half g_w2 [EXPAND * D_MODEL * D_MODEL];// fc_w^T
__device__ __half g_w3 [EXPAND * D_MODEL * D_MODEL];// fc2_w^T
__device__ float  g_x1 [ROWS * D_MODEL];

// ================= helpers ==================================================
__device__ __forceinline__ uint32_t smem_to_u32(const void* p) {
    uint32_t a;
    asm("{ .reg .u64 t; cvta.to.shared.u64 t, %1; cvt.u32.u64 %0, t; }" : "=r"(a) : "l"(p));
    return a;
}
#define SMEM_SWIZZLE_128B(off) ((off) ^ (((off) >> 3) & 0x70))

#define CP_ASYNC16(dst_u32, src_ptr) \
    asm volatile("cp.async.cg.shared.global [%0], [%1], 16;" :: "r"(dst_u32), "l"(src_ptr))
#define CP_COMMIT() asm volatile("cp.async.commit_group;" ::: "memory")
#define CP_WAIT0()  asm volatile("cp.async.wait_group 0;" ::: "memory")
#define CP_WAIT1()  asm volatile("cp.async.wait_group 1;" ::: "memory")

#define LDMATRIX_X4(r0, r1, r2, r3, addr) \
    asm volatile("ldmatrix.sync.aligned.m8n8.x4.shared.b16 {%0,%1,%2,%3}, [%4];" \
        : "=r"(r0), "=r"(r1), "=r"(r2), "=r"(r3) : "r"(addr))
#define LDMATRIX_X4_TRANS(r0, r1, r2, r3, addr) \
    asm volatile("ldmatrix.sync.aligned.m8n8.x4.trans.shared.b16 {%0,%1,%2,%3}, [%4];" \
        : "=r"(r0), "=r"(r1), "=r"(r2), "=r"(r3) : "r"(addr))

__device__ __forceinline__ void hmma32(float* c, const uint32_t* a, const uint32_t* b) {
    asm volatile(
        "mma.sync.aligned.m16n8k16.row.col.f32.f16.f16.f32 "
        "{%0,%1,%2,%3}, {%4,%5,%6,%7}, {%8,%9}, {%0,%1,%2,%3};"
        : "+f"(c[0]), "+f"(c[1]), "+f"(c[2]), "+f"(c[3])
        : "r"(a[0]), "r"(a[1]), "r"(a[2]), "r"(a[3]), "r"(b[0]), "r"(b[1]));
}

__device__ __forceinline__ uint32_t pack_f2h2(float a, float b) {
    __half2 t; t.x = __float2half_rn(a); t.y = __float2half_rn(b);
    return *(uint32_t*)&t;
}

// ---------------- LayerNorm -> fp16 ------------------------------------------
__global__ __launch_bounds__(256)
void ln_kernel(const float* __restrict__ x, const float* __restrict__ w,
               const float* __restrict__ b, __half* __restrict__ o) {
    int row = blockIdx.x;
    const float4* xr = (const float4*)(x + (size_t)row * D_MODEL);
    float4 v = xr[threadIdx.x];
    float s  = v.x + v.y + v.z + v.w;
    float ss = v.x*v.x + v.y*v.y + v.z*v.z + v.w*v.w;
    #pragma unroll
    for (int of = 16; of; of >>= 1) {
        s  += __shfl_down_sync(0xffffffffu, s,  of);
        ss += __shfl_down_sync(0xffffffffu, ss, of);
    }
    __shared__ float rs[8], rss[8];
    __shared__ float mu_s, rstd_s;
    int wid = threadIdx.x >> 5, lid = threadIdx.x & 31;
    if (lid == 0) { rs[wid] = s; rss[wid] = ss; }
    __syncthreads();
    if (threadIdx.x == 0) {
        float ts = 0.f, tss = 0.f;
        #pragma unroll
        for (int i = 0; i < 8; i++) { ts += rs[i]; tss += rss[i]; }
        float mu  = ts * (1.0f / D_MODEL);
        float var = tss * (1.0f / D_MODEL) - mu * mu;
        mu_s = mu; rstd_s = rsqrtf(var + 1e-5f);
    }
    __syncthreads();
    float mu = mu_s, rstd = rstd_s;
    float4 wv = ((const float4*)w)[threadIdx.x];
    float4 bv = ((const float4*)b)[threadIdx.x];
    float o0 = (v.x - mu) * rstd * wv.x + bv.x;
    float o1 = (v.y - mu) * rstd * wv.y + bv.y;
    float o2 = (v.z - mu) * rstd * wv.z + bv.z;
    float o3 = (v.w - mu) * rstd * wv.w + bv.w;
    uint2 pk;
    pk.x = pack_f2h2(o0, o1);
    pk.y = pack_f2h2(o2, o3);
    *(uint2*)(o + (size_t)row * D_MODEL + threadIdx.x * 4) = pk;
}

// ---------------- weight transpose: W[K,N] -> Wt[N,K] fp16 -------------------
__global__ __launch_bounds__(256)
void wtrans_kernel(const float* __restrict__ W, __half* __restrict__ wt,
                   int K, int N) {
    __shared__ float t[32][33];
    int n0 = blockIdx.x * 32, k0 = blockIdx.y * 32;
    int tx = threadIdx.x & 31, ty = threadIdx.x >> 5;
    #pragma unroll
    for (int i = 0; i < 32; i += 8)
        t[ty + i][tx] = W[(size_t)(k0 + ty + i) * N + n0 + tx];
    __syncthreads();
    #pragma unroll
    for (int i = 0; i < 32; i += 8) {
        float v = t[tx][ty + i];
        wt[(size_t)(n0 + ty + i) * K + k0 + tx] = __float2half_rn(v);
    }
}

// ---------------- fp16 HMMA GEMM: C = A @ B^T --------------------------------
// CTA tile 128x128, BK=64 (SW128), 3-stage cp.async ring, 2 CTAs/SM.
// B-fragments software-pipelined across the ks loop.
// EPI: 0 bias -> f32 C; 1 bias+residual -> f32 C; 2 bias+GELU -> f16; 3 bias -> f16
#define GEMM_STAGE_BYTES 32768           // A 16K | B 16K
#define GEMM_NSTAGE 3
#define GEMM_SMEM_BYTES (GEMM_NSTAGE * GEMM_STAGE_BYTES)

template<int EPI>
__global__ __launch_bounds__(256, 2)
void gemm_tc(const __half* __restrict__ A, const __half* __restrict__ B,
             const float* __restrict__ bias, const float* __restrict__ res,
             float* __restrict__ C, __half* __restrict__ Ch,
             int M, int N, int K) {
    extern __shared__ __align__(128) char smem[];
    uint32_t su = smem_to_u32(smem);

    const int tid  = threadIdx.x;
    const int lane = tid & 31;
    const int wid  = tid >> 5;
    const int wm   = (wid & 1) * 64;    // 2 warps along M
    const int wn   = (wid >> 1) * 32;   // 4 warps along N
    const int m0 = blockIdx.y * 128, n0 = blockIdx.x * 128;

    float acc[4][4][4];
    #pragma unroll
    for (int i = 0; i < 4; i++)
        #pragma unroll
        for (int j = 0; j < 4; j++)
            #pragma unroll
            for (int k = 0; k < 4; k++) acc[i][j][k] = 0.f;

    const int nkt = K >> 6;              // K / 64
    const int lrow16 = lane & 15;
    const int khalf  = (lane >> 4) << 4; // 0 / 16 bytes

    int lr[4];
    int lc[4];
    uint32_t ld[4];
    #pragma unroll
    for (int j = 0; j < 4; j++) {
        int e = j * 256 + tid;
        lr[j] = e >> 3;
        lc[j] = e & 7;
        ld[j] = SMEM_SWIZZLE_128B((uint32_t)(lr[j] * 128 + lc[j] * 16));
    }

    auto issue_loads = [&](int kt) {
        uint32_t base = su + (kt % GEMM_NSTAGE) * GEMM_STAGE_BYTES;
        int k0 = kt << 6;
        #pragma unroll
        for (int j = 0; j < 4; j++) {
            size_t a0 = (size_t)(m0 + lr[j]) * K + k0 + lc[j] * 8;
            size_t b0 = (size_t)(n0 + lr[j]) * K + k0 + lc[j] * 8;
            CP_ASYNC16(base +         ld[j], A + a0);
            CP_ASYNC16(base + 16384 + ld[j], B + b0);
        }
        CP_COMMIT();
    };

    // per-warp B-row ldsm addresses (two 16-row groups along this warp's 32 N)
    const int br0 = wn + lrow16;
    const int br1 = wn + 16 + lrow16;

    issue_loads(0);
    if (nkt > 1) issue_loads(1);

    for (int kt = 0; kt < nkt; kt++) {
        if (kt + 1 < nkt) { CP_WAIT1(); } else { CP_WAIT0(); }
        __syncthreads();
        if (kt + 2 < nkt) issue_loads(kt + 2);

        uint32_t base = su + (kt % GEMM_NSTAGE) * GEMM_STAGE_BYTES;

        // prefetch B-frags for ks = 0
        uint32_t bh[4][2], bhn[4][2];
        {
            const uint32_t kb0 = (uint32_t)khalf;
            uint32_t off0 = (uint32_t)(br0 * 128) + (kb0 ^ (uint32_t)((br0 & 7) << 4));
            uint32_t off1 = (uint32_t)(br1 * 128) + (kb0 ^ (uint32_t)((br1 & 7) << 4));
            uint32_t t0, t1, t2, t3;
            LDMATRIX_X4(t0, t1, t2, t3, base + 16384 + off0);
            bh[0][0] = t0; bh[0][1] = t2; bh[1][0] = t1; bh[1][1] = t3;
            LDMATRIX_X4(t0, t1, t2, t3, base + 16384 + off1);
            bh[2][0] = t0; bh[2][1] = t2; bh[3][0] = t1; bh[3][1] = t3;
        }

        #pragma unroll
        for (int ks = 0; ks < 4; ks++) {
            // prefetch B-frags for ks+1 while HMMAs for ks are in flight
            if (ks < 3) {
                const uint32_t kbn = (uint32_t)((ks + 1) * 32 + khalf);
                uint32_t off0 = (uint32_t)(br0 * 128) + (kbn ^ (uint32_t)((br0 & 7) << 4));
                uint32_t off1 = (uint32_t)(br1 * 128) + (kbn ^ (uint32_t)((br1 & 7) << 4));
                uint32_t t0, t1, t2, t3;
                LDMATRIX_X4(t0, t1, t2, t3, base + 16384 + off0);
                bhn[0][0] = t0; bhn[0][1] = t2; bhn[1][0] = t1; bhn[1][1] = t3;
                LDMATRIX_X4(t0, t1, t2, t3, base + 16384 + off1);
                bhn[2][0] = t0; bhn[2][1] = t2; bhn[3][0] = t1; bhn[3][1] = t3;
            }
            const uint32_t kb = (uint32_t)(ks * 32 + khalf);
            #pragma unroll
            for (int mt = 0; mt < 4; mt++) {
                int r = wm + mt * 16 + lrow16;
                uint32_t off = (uint32_t)(r * 128) + (kb ^ (uint32_t)((r & 7) << 4));
                uint32_t ah[4];
                LDMATRIX_X4(ah[0], ah[1], ah[2], ah[3], base + off);
                #pragma unroll
                for (int nt = 0; nt < 4; nt++)
                    hmma32(acc[mt][nt], ah, bh[nt]);
            }
            if (ks < 3) {
                #pragma unroll
                for (int nt = 0; nt < 4; nt++) {
                    bh[nt][0] = bhn[nt][0];
                    bh[nt][1] = bhn[nt][1];
                }
            }
        }
    }

    const int rbase = m0 + wm + (lane >> 2);
    const int cbase = n0 + wn + (lane & 3) * 2;
    #pragma unroll
    for (int mt = 0; mt < 4; mt++) {
        #pragma unroll
        for (int nt = 0; nt < 4; nt++) {
            int col = cbase + nt * 8;
            float b0 = bias[col], b1 = bias[col + 1];
            #pragma unroll
            for (int half = 0; half < 2; half++) {
                int row = rbase + mt * 16 + half * 8;
                float v0 = acc[mt][nt][half * 2]     + b0;
                float v1 = acc[mt][nt][half * 2 + 1] + b1;
                if (EPI == 1) {
                    float2 rv = *(const float2*)(res + (size_t)row * N + col);
                    v0 += rv.x; v1 += rv.y;
                }
                if (EPI == 2) {
                    v0 = 0.5f * v0 * (1.0f + erff(v0 * 0.70710678118654752f));
                    v1 = 0.5f * v1 * (1.0f + erff(v1 * 0.70710678118654752f));
                }
                if (EPI >= 2) {
                    *(uint32_t*)(Ch + (size_t)row * N + col) = pack_f2h2(v0, v1);
                } else {
                    float2 o; o.x = v0; o.y = v1;
                    *(float2*)(C + (size_t)row * N + col) = o;
                }
            }
        }
    }
}

// ---------------- tensor-core flash attention --------------------------------
// 256 threads = 8 warps; each warp owns one 16-row q block (q-tile = 128).
// KV tiles of 128 (Bc=128), double buffered. Pure fp16 operands, fp32 acc.
#define ATTN_SMEM (16384 + 2 * 32768)   // Q 16K + 2 KV stages (K 16K + V 16K)

__global__ __launch_bounds__(256)
void attn_tc(const __half* __restrict__ qkv, __half* __restrict__ y) {
    extern __shared__ __align__(128) char smem[];
    uint32_t su = smem_to_u32(smem);
    const int tid = threadIdx.x, lane = tid & 31, w = tid >> 5;  // 8 warps
    const int bh = blockIdx.y, b = bh >> 4, h = bh & 15;
    const int qt = (int)gridDim.x - 1 - (int)blockIdx.x;   // big tiles first
    const int ntiles = qt + 1;

    const uint32_t QH = su;
    const size_t qrow0 = (size_t)(b * TT + qt * 128);

    // Q tile: 128 rows x 64 cols fp16 (128B rows), SW128
    #pragma unroll
    for (int j = 0; j < 4; j++) {
        int e = j * 256 + tid; int r = e >> 3, c = e & 7;
        uint32_t d = SMEM_SWIZZLE_128B((uint32_t)(r * 128 + c * 16));
        CP_ASYNC16(QH + d, qkv + (qrow0 + r) * (3 * D_MODEL) + h * 64 + c * 8);
    }
    auto issue_kv = [&](int kt, int s) {
        uint32_t base = su + 16384 + s * 32768;
        size_t krow0 = (size_t)(b * TT + kt * 128);
        #pragma unroll
        for (int j = 0; j < 4; j++) {
            int e = j * 256 + tid; int r = e >> 3, c = e & 7;
            uint32_t d = SMEM_SWIZZLE_128B((uint32_t)(r * 128 + c * 16));
            size_t ksrc = (krow0 + r) * (3 * D_MODEL) + D_MODEL + h * 64 + c * 8;
            CP_ASYNC16(base +         d, qkv + ksrc);
            CP_ASYNC16(base + 16384 + d, qkv + ksrc + D_MODEL);
        }
        CP_COMMIT();
    };
    issue_kv(0, 0);

    float O[8][4];
    #pragma unroll
    for (int dt = 0; dt < 8; dt++)
        #pragma unroll
        for (int k = 0; k < 4; k++) O[dt][k] = 0.f;
    float mrow0 = -1e30f, mrow1 = -1e30f;
    float lrow0 = 0.f, lrow1 = 0.f;

    const int lrow16 = lane & 15;
    const uint32_t khalfB = (uint32_t)((lane >> 4) << 4);
    const int r4 = lane >> 2, c2 = (lane & 3) * 2;
    const int qmt = qt * 128 + w * 16;          // first q row of this warp
    const int q0  = qmt + r4;                   // thread's first row

    for (int kt = 0; kt < ntiles; kt++) {
        int s = kt & 1;
        if (kt + 1 < ntiles) { issue_kv(kt + 1, s ^ 1); CP_WAIT1(); }
        else                 { CP_WAIT0(); }
        __syncthreads();
        const uint32_t KB = su + 16384 + s * 32768;
        const uint32_t VB = KB + 16384;

        // ---- S = Q K^T : 16 q rows x 128 kv cols ----
        float sa[16][4];
        #pragma unroll
        for (int nt = 0; nt < 16; nt++)
            #pragma unroll
            for (int k = 0; k < 4; k++) sa[nt][k] = 0.f;

        #pragma unroll
        for (int ks = 0; ks < 4; ks++) {
            const uint32_t kb = (uint32_t)(ks * 32) + khalfB;
            const int ar = w * 16 + lrow16;
            uint32_t aoff = (uint32_t)(ar * 128) + (kb ^ (uint32_t)((ar & 7) << 4));
            uint32_t ah[4];
            LDMATRIX_X4(ah[0], ah[1], ah[2], ah[3], QH + aoff);
            uint32_t kh[16][2];
            #pragma unroll
            for (int p = 0; p < 8; p++) {
                const int br = p * 16 + lrow16;
                uint32_t boff = (uint32_t)(br * 128) + (kb ^ (uint32_t)((br & 7) << 4));
                uint32_t t0, t1, t2, t3;
                LDMATRIX_X4(t0, t1, t2, t3, KB + boff);
                kh[p*2][0] = t0; kh[p*2][1] = t2;
                kh[p*2+1][0] = t1; kh[p*2+1][1] = t3;
            }
            #pragma unroll
            for (int nt = 0; nt < 16; nt++)
                hmma32(sa[nt], ah, kh[nt]);
        }

        #pragma unroll
        for (int nt = 0; nt < 16; nt++)
            #pragma unroll
            for (int k = 0; k < 4; k++) sa[nt][k] *= 0.125f;

        // ---- causal mask (only the diagonal tile) ----
        if (kt == qt) {
            #pragma unroll
            for (int nt = 0; nt < 16; nt++) {
                int kv0 = kt * 128 + nt * 8 + c2;
                if (kv0     > q0)     sa[nt][0] = -1e30f;
                if (kv0 + 1 > q0)     sa[nt][1] = -1e30f;
                if (kv0     > q0 + 8) sa[nt][2] = -1e30f;
                if (kv0 + 1 > q0 + 8) sa[nt][3] = -1e30f;
            }
        }

        // ---- online softmax ----
        float tm0 = -1e30f, tm1 = -1e30f;
        #pragma unroll
        for (int nt = 0; nt < 16; nt++) {
            tm0 = fmaxf(tm0, fmaxf(sa[nt][0], sa[nt][1]));
            tm1 = fmaxf(tm1, fmaxf(sa[nt][2], sa[nt][3]));
        }
        tm0 = fmaxf(tm0, __shfl_xor_sync(0xffffffffu, tm0, 1));
        tm0 = fmaxf(tm0, __shfl_xor_sync(0xffffffffu, tm0, 2));
        tm1 = fmaxf(tm1, __shfl_xor_sync(0xffffffffu, tm1, 1));
        tm1 = fmaxf(tm1, __shfl_xor_sync(0xffffffffu, tm1, 2));
        float nm0 = fmaxf(mrow0, tm0), nm1 = fmaxf(mrow1, tm1);
        float cor0 = __expf(mrow0 - nm0), cor1 = __expf(mrow1 - nm1);
        mrow0 = nm0; mrow1 = nm1;

        float ps0 = 0.f, ps1 = 0.f;
        uint32_t Ph[16][2];
        #pragma unroll
        for (int nt = 0; nt < 16; nt++) {
            float p00 = __expf(sa[nt][0] - nm0), p01 = __expf(sa[nt][1] - nm0);
            float p10 = __expf(sa[nt][2] - nm1), p11 = __expf(sa[nt][3] - nm1);
            ps0 += p00 + p01; ps1 += p10 + p11;
            Ph[nt][0] = pack_f2h2(p00, p01);
            Ph[nt][1] = pack_f2h2(p10, p11);
        }
        ps0 += __shfl_xor_sync(0xffffffffu, ps0, 1);
        ps0 += __shfl_xor_sync(0xffffffffu, ps0, 2);
        ps1 += __shfl_xor_sync(0xffffffffu, ps1, 1);
        ps1 += __shfl_xor_sync(0xffffffffu, ps1, 2);
        lrow0 = lrow0 * cor0 + ps0;
        lrow1 = lrow1 * cor1 + ps1;

        #pragma unroll
        for (int dt = 0; dt < 8; dt++) {
            O[dt][0] *= cor0; O[dt][1] *= cor0;
            O[dt][2] *= cor1; O[dt][3] *= cor1;
        }

        // ---- O += P V : P 16x128, V 128x64 ----
        #pragma unroll
        for (int ks = 0; ks < 8; ks++) {
            uint32_t vh[8][2];
            #pragma unroll
            for (int dc = 0; dc < 4; dc++) {
                const int vr = ks * 16 + lrow16;
                uint32_t voff = (uint32_t)(vr * 128) +
                    (((uint32_t)(dc * 32) + khalfB) ^ (uint32_t)((vr & 7) << 4));
                uint32_t t0, t1, t2, t3;
                LDMATRIX_X4_TRANS(t0, t1, t2, t3, VB + voff);
                vh[dc*2][0] = t0; vh[dc*2][1] = t1;
                vh[dc*2+1][0] = t2; vh[dc*2+1][1] = t3;
            }
            uint32_t aph[4] = {Ph[2*ks][0], Ph[2*ks][1], Ph[2*ks+1][0], Ph[2*ks+1][1]};
            #pragma unroll
            for (int dt = 0; dt < 8; dt++)
                hmma32(O[dt], aph, vh[dt]);
        }
        __syncthreads();
    } // kt

    float inv0 = 1.0f / lrow0, inv1 = 1.0f / lrow1;
    size_t row0 = qrow0 + w * 16 + r4;
    size_t row1 = row0 + 8;
    #pragma unroll
    for (int dt = 0; dt < 8; dt++) {
        int col = h * 64 + dt * 8 + c2;
        *(uint32_t*)(y + row0 * D_MODEL + col) = pack_f2h2(O[dt][0] * inv0, O[dt][1] * inv0);
        *(uint32_t*)(y + row1 * D_MODEL + col) = pack_f2h2(O[dt][2] * inv1, O[dt][3] * inv1);
    }
}

// ---------------- streams/events (created pre-main, outside mem checkpoints) -
struct GraphForks {
    cudaStream_t s1;
    cudaEvent_t fork, evA, evB, evC, evD;
    GraphForks() {
        cudaStreamCreateWithFlags(&s1, cudaStreamNonBlocking);
        cudaEventCreateWithFlags(&fork, cudaEventDisableTiming);
        cudaEventCreateWithFlags(&evA,  cudaEventDisableTiming);
        cudaEventCreateWithFlags(&evB,  cudaEventDisableTiming);
        cudaEventCreateWithFlags(&evC,  cudaEventDisableTiming);
        cudaEventCreateWithFlags(&evD,  cudaEventDisableTiming);
    }
};
static GraphForks g_forks;

// ---------------- launch ----------------------------------------------------
extern "C" void kernel_launch(void* const* d_in, const int* in_sizes, int n_in,
                              void* d_out, int out_size) {
    const float* x      = (const float*)d_in[0];
    const float* ln1_w  = (const float*)d_in[1];
    const float* ln1_b  = (const float*)d_in[2];
    const float* attn_w = (const float*)d_in[3];
    const float* attn_b = (const float*)d_in[4];
    const float* proj_w = (const float*)d_in[5];
    const float* proj_b = (const float*)d_in[6];
    const float* ln2_w  = (const float*)d_in[7];
    const float* ln2_b  = (const float*)d_in[8];
    const float* fc_w   = (const float*)d_in[9];
    const float* fc_b   = (const float*)d_in[10];
    const float* fc2_w  = (const float*)d_in[11];
    const float* fc2_b  = (const float*)d_in[12];
    float* out = (float*)d_out;

    __half *a, *hh, *w0, *w1, *w2, *w3;
    float *x1;
    cudaGetSymbolAddress((void**)&a,  g_a);
    cudaGetSymbolAddress((void**)&hh, g_h);
    cudaGetSymbolAddress((void**)&w0, g_w0);
    cudaGetSymbolAddress((void**)&w1, g_w1);
    cudaGetSymbolAddress((void**)&w2, g_w2);
    cudaGetSymbolAddress((void**)&w3, g_w3);
    cudaGetSymbolAddress((void**)&x1, g_x1);

    static bool attr_set = false;
    if (!attr_set) {
        cudaFuncSetAttribute(gemm_tc<0>, cudaFuncAttributeMaxDynamicSharedMemorySize, GEMM_SMEM_BYTES);
        cudaFuncSetAttribute(gemm_tc<1>, cudaFuncAttributeMaxDynamicSharedMemorySize, GEMM_SMEM_BYTES);
        cudaFuncSetAttribute(gemm_tc<2>, cudaFuncAttributeMaxDynamicSharedMemorySize, GEMM_SMEM_BYTES);
        cudaFuncSetAttribute(gemm_tc<3>, cudaFuncAttributeMaxDynamicSharedMemorySize, GEMM_SMEM_BYTES);
        cudaFuncSetAttribute(attn_tc,    cudaFuncAttributeMaxDynamicSharedMemorySize, ATTN_SMEM);
        attr_set = true;
    }

    cudaStream_t s0 = 0;
    cudaStream_t s1 = g_forks.s1;

    // Fork: weight transposes on s1 (fills launch-gap bubbles).
    cudaEventRecord(g_forks.fork, s0);
    cudaStreamWaitEvent(s1, g_forks.fork, 0);
    wtrans_kernel<<<dim3(3 * D_MODEL / 32, D_MODEL / 32), 256, 0, s1>>>(attn_w, w0, D_MODEL, 3 * D_MODEL);
    cudaEventRecord(g_forks.evA, s1);
    wtrans_kernel<<<dim3(D_MODEL / 32, D_MODEL / 32), 256, 0, s1>>>(proj_w, w1, D_MODEL, D_MODEL);
    cudaEventRecord(g_forks.evB, s1);
    wtrans_kernel<<<dim3(EXPAND * D_MODEL / 32, D_MODEL / 32), 256, 0, s1>>>(fc_w, w2, D_MODEL, EXPAND * D_MODEL);
    cudaEventRecord(g_forks.evC, s1);
    wtrans_kernel<<<dim3(D_MODEL / 32, EXPAND * D_MODEL / 32), 256, 0, s1>>>(fc2_w, w3, EXPAND * D_MODEL, D_MODEL);
    cudaEventRecord(g_forks.evD, s1);

    // Main chain on s0.
    ln_kernel<<<ROWS, 256, 0, s0>>>(x, ln1_w, ln1_b, a);
    cudaStreamWaitEvent(s0, g_forks.evA, 0);
    gemm_tc<3><<<dim3(3 * D_MODEL / 128, ROWS / 128), 256, GEMM_SMEM_BYTES, s0>>>(
        a, w0, attn_b, nullptr, nullptr, hh, ROWS, 3 * D_MODEL, D_MODEL);
    attn_tc<<<dim3(TT / 128, BB * N_HEAD), 256, ATTN_SMEM, s0>>>(hh, a);
    cudaStreamWaitEvent(s0, g_forks.evB, 0);
    gemm_tc<1><<<dim3(D_MODEL / 128, ROWS / 128), 256, GEMM_SMEM_BYTES, s0>>>(
        a, w1, proj_b, x, x1, nullptr, ROWS, D_MODEL, D_MODEL);
    ln_kernel<<<ROWS, 256, 0, s0>>>(x1, ln2_w, ln2_b, a);
    cudaStreamWaitEvent(s0, g_forks.evC, 0);
    gemm_tc<2><<<dim3(EXPAND * D_MODEL / 128, ROWS / 128), 256, GEMM_SMEM_BYTES, s0>>>(
        a, w2, fc_b, nullptr, nullptr, hh, ROWS, EXPAND * D_MODEL, D_MODEL);
    cudaStreamWaitEvent(s0, g_forks.evD, 0);
    gemm_tc<1><<<dim3(D_MODEL / 128, ROWS / 128), 256, GEMM_SMEM_BYTES, s0>>>(
        hh, w3, fc2_b, x1, out, nullptr, ROWS, D_MODEL, EXPAND * D_MODEL);
}